// round 10
// baseline (speedup 1.0000x reference)
#include <cuda_runtime.h>
#include <cuda_bf16.h>
#include <cstdint>

// 4096-pt FWHT, 8192 rows fp32.
// Persistent-CTA version of the R4/R9-proven pipeline:
//   grid = 148*6 = 888 CTAs (exact resident set at 33KB smem/CTA), each CTA
//   steals rows from a global atomic counter and streams them through a
//   double-buffered cp.async.cg pipeline that never drains between rows.
// Radix 64x64: Round A butterflies element bits [7:2], Round B bits
// {[11:8],[1:0]}. Additive skew phys(e) = e + (e>>8)*4 -> all smem patterns
// bank-conflict-free, folds to LDS immediates. Packed fma.rn.f32x2 math.

#define ROW    4096
#define TPR    64
#define SROW   4160          // skewed row words (max phys 4155, pad to 16B mult)
#define GRID   (148 * 6)

__device__ unsigned int g_row_ctr;

__global__ void init_ctr_kernel() { g_row_ctr = 0u; }

__device__ __forceinline__ float2 ffma2(float2 b, float2 m, float2 a) {
    float2 r;
    asm("fma.rn.f32x2 %0, %1, %2, %3;"
        : "=l"(reinterpret_cast<unsigned long long&>(r))
        : "l"(reinterpret_cast<const unsigned long long&>(b)),
          "l"(reinterpret_cast<const unsigned long long&>(m)),
          "l"(reinterpret_cast<const unsigned long long&>(a)));
    return r;
}

__device__ __forceinline__ float2 fmul2(float2 a, float2 m) {
    float2 r;
    asm("mul.rn.f32x2 %0, %1, %2;"
        : "=l"(reinterpret_cast<unsigned long long&>(r))
        : "l"(reinterpret_cast<const unsigned long long&>(a)),
          "l"(reinterpret_cast<const unsigned long long&>(m)));
    return r;
}

// 64-pt FWHT over 32 packed float2 (v[p] = (elem 2p, elem 2p+1)).
__device__ __forceinline__ void fwht64p(float2* v) {
    const float2 P1 = make_float2(1.0f, 1.0f);
    const float2 M1 = make_float2(-1.0f, -1.0f);
#pragma unroll
    for (int p = 0; p < 32; p++) {           // h=1 (intra-pair)
        float lo = v[p].x, hi = v[p].y;
        v[p].x = lo + hi;
        v[p].y = lo - hi;
    }
#pragma unroll
    for (int h = 1; h < 32; h <<= 1) {       // h=2..64 packed
#pragma unroll
        for (int p = 0; p < 32; p++) {
            if ((p & h) == 0) {
                float2 a = v[p], b = v[p + h];
                v[p]     = ffma2(b, P1, a);
                v[p + h] = ffma2(b, M1, a);
            }
        }
    }
}

__device__ __forceinline__ void cp_async16(uint32_t dst_smem, const void* src) {
    asm volatile("cp.async.cg.shared.global [%0], [%1], 16;"
                 :: "r"(dst_smem), "l"(src) : "memory");
}
__device__ __forceinline__ void cp_commit() {
    asm volatile("cp.async.commit_group;" ::: "memory");
}
template <int N>
__device__ __forceinline__ void cp_wait() {
    asm volatile("cp.async.wait_group %0;" :: "n"(N) : "memory");
}

// Stage one row into a smem buffer: float4 q = i*64 + t (coalesced),
// element e = 256*i + 4*t -> skewed word 260*i + 4*t (16B aligned).
__device__ __forceinline__ void stage_row(uint32_t sbuf, const float4* x4, int t) {
#pragma unroll
    for (int i = 0; i < 16; i++)
        cp_async16(sbuf + (260u * i + 4u * t) * 4u, x4 + i * 64 + t);
    cp_commit();
}

__global__ void __launch_bounds__(TPR)
fwht4096_kernel(const float* __restrict__ in, float* __restrict__ out, int nrows) {
    __shared__ __align__(16) float s[2 * SROW];
    __shared__ unsigned int sh_row;

    const int t = threadIdx.x;

    uint32_t sbase;
    asm("{ .reg .u64 tmp; cvta.to.shared.u64 tmp, %1; cvt.u32.u64 %0, tmp; }"
        : "=r"(sbase) : "l"(s));
    const uint32_t sbuf0 = sbase;
    const uint32_t sbuf1 = sbase + SROW * 4u;

    // Prologue: steal first row, stage into buffer 0.
    if (t == 0) sh_row = atomicAdd(&g_row_ctr, 1u);
    __syncthreads();
    unsigned int row_cur = sh_row;
    if (row_cur < (unsigned)nrows)
        stage_row(sbuf0, reinterpret_cast<const float4*>(in + (size_t)row_cur * ROW), t);

    const int j = t >> 2, r = t & 3;   // round-A ownership
    int cur = 0;

    while (row_cur < (unsigned)nrows) {
        // Steal the next row and prefetch it into the other buffer.
        if (t == 0) sh_row = atomicAdd(&g_row_ctr, 1u);
        __syncthreads();                       // broadcast sh_row
        const unsigned int row_next = sh_row;

        if (row_next < (unsigned)nrows) {
            stage_row(cur ? sbuf0 : sbuf1,
                      reinterpret_cast<const float4*>(in + (size_t)row_next * ROW), t);
            cp_wait<1>();   // current row's group complete
        } else {
            cp_wait<0>();
        }
        __syncthreads();    // row_cur data visible to all threads

        float* sm = s + cur * SROW;

        // ---- Round A: thread (j,r) owns e = j*256 + m*4 + r, m = 0..63.
        // Skewed word = 260*j + 4*m + r; banks (4j+r) mod 32 per phase -> clean.
        {
            float* base = sm + 260 * j + r;
            float2 v[32];
#pragma unroll
            for (int p = 0; p < 32; p++)
                v[p] = make_float2(base[8 * p], base[8 * p + 4]);
            fwht64p(v);   // butterflies bits [7:2]
#pragma unroll
            for (int p = 0; p < 32; p++) {
                base[8 * p]     = v[p].x;
                base[8 * p + 4] = v[p].y;
            }
        }
        __syncthreads();   // round A scatter -> round B gather

        // ---- Round B: thread t owns e = jj*256 + 4*t + rr (LDS.128 gather),
        // butterflies bits {[11:8],[1:0]}, then scaled coalesced STG.128.
        {
            float2 w[32];
#pragma unroll
            for (int jj = 0; jj < 16; jj++) {
                float4 q = *reinterpret_cast<const float4*>(sm + 260 * jj + 4 * t);
                w[2 * jj]     = make_float2(q.x, q.y);
                w[2 * jj + 1] = make_float2(q.z, q.w);
            }
            fwht64p(w);

            const float2 SC = make_float2(1.0f / 64.0f, 1.0f / 64.0f);
            float4* y4 = reinterpret_cast<float4*>(out + (size_t)row_cur * ROW);
#pragma unroll
            for (int jj = 0; jj < 16; jj++) {
                float2 lo = fmul2(w[2 * jj], SC);
                float2 hi = fmul2(w[2 * jj + 1], SC);
                float4 o;
                o.x = lo.x; o.y = lo.y; o.z = hi.x; o.w = hi.y;
                y4[jj * 64 + t] = o;
            }
        }
        // Trailing barrier: protects buf[cur] before the next iteration's
        // prefetch overwrites it.
        __syncthreads();

        row_cur = row_next;
        cur ^= 1;
    }
}

extern "C" void kernel_launch(void* const* d_in, const int* in_sizes, int n_in,
                              void* d_out, int out_size) {
    const float* x = (const float*)d_in[0];
    float* y = (float*)d_out;
    int total = in_sizes[0];
    int nrows = total / ROW;                 // 8192
    init_ctr_kernel<<<1, 1>>>();
    fwht4096_kernel<<<GRID, TPR>>>(x, y, nrows);
}

// round 11
// speedup vs baseline: 1.0448x; 1.0448x over previous
#include <cuda_runtime.h>
#include <cuda_bf16.h>
#include <cstdint>

// 4096-pt FWHT, 8192 rows fp32.
// R9-champion pipeline: one 64-thread CTA, rows_per_cta = 2 (grid 4096),
// double-buffered cp.async.cg (stage k+1 -> wait<1> -> barrier -> round A ->
// barrier -> round B -> STG -> trailing barrier).
// Radix 64x64: Round A butterflies element bits [7:2], Round B bits
// {[11:8],[1:0]}. Additive skew phys(e) = e + (e>>8)*4 -> all smem patterns
// bank-conflict-free, folds to LDS immediates. Packed fma.rn.f32x2 math.
// NEW vs R9: SROW = 4156 exactly (max phys 4155; 4156*4 B is 16B-aligned) ->
// 33248 B/CTA -> 7 CTAs/SM resident (232.7KB <= 228..233.5KB carveout) ->
// 14 warps/SM and 3.95->4-wave quantization (98.8% schedule efficiency).

#define ROW    4096
#define TPR    64
#define SROW   4156          // skewed row words, exact (16B-aligned: 4156*4=16624)
#define RPC    2

__device__ __forceinline__ float2 ffma2(float2 b, float2 m, float2 a) {
    float2 r;
    asm("fma.rn.f32x2 %0, %1, %2, %3;"
        : "=l"(reinterpret_cast<unsigned long long&>(r))
        : "l"(reinterpret_cast<const unsigned long long&>(b)),
          "l"(reinterpret_cast<const unsigned long long&>(m)),
          "l"(reinterpret_cast<const unsigned long long&>(a)));
    return r;
}

__device__ __forceinline__ float2 fmul2(float2 a, float2 m) {
    float2 r;
    asm("mul.rn.f32x2 %0, %1, %2;"
        : "=l"(reinterpret_cast<unsigned long long&>(r))
        : "l"(reinterpret_cast<const unsigned long long&>(a)),
          "l"(reinterpret_cast<const unsigned long long&>(m)));
    return r;
}

// 64-pt FWHT over 32 packed float2 (v[p] = (elem 2p, elem 2p+1)).
__device__ __forceinline__ void fwht64p(float2* v) {
    const float2 P1 = make_float2(1.0f, 1.0f);
    const float2 M1 = make_float2(-1.0f, -1.0f);
#pragma unroll
    for (int p = 0; p < 32; p++) {           // h=1 (intra-pair)
        float lo = v[p].x, hi = v[p].y;
        v[p].x = lo + hi;
        v[p].y = lo - hi;
    }
#pragma unroll
    for (int h = 1; h < 32; h <<= 1) {       // h=2..64 packed
#pragma unroll
        for (int p = 0; p < 32; p++) {
            if ((p & h) == 0) {
                float2 a = v[p], b = v[p + h];
                v[p]     = ffma2(b, P1, a);
                v[p + h] = ffma2(b, M1, a);
            }
        }
    }
}

__device__ __forceinline__ void cp_async16(uint32_t dst_smem, const void* src) {
    asm volatile("cp.async.cg.shared.global [%0], [%1], 16;"
                 :: "r"(dst_smem), "l"(src) : "memory");
}
__device__ __forceinline__ void cp_commit() {
    asm volatile("cp.async.commit_group;" ::: "memory");
}
template <int N>
__device__ __forceinline__ void cp_wait() {
    asm volatile("cp.async.wait_group %0;" :: "n"(N) : "memory");
}

// Stage one row into a smem buffer: float4 q = i*64 + t (coalesced),
// element e = 256*i + 4*t -> skewed word 260*i + 4*t (16B aligned).
__device__ __forceinline__ void stage_row(uint32_t sbuf, const float4* x4, int t) {
#pragma unroll
    for (int i = 0; i < 16; i++)
        cp_async16(sbuf + (260u * i + 4u * t) * 4u, x4 + i * 64 + t);
    cp_commit();
}

__global__ void __launch_bounds__(TPR)
fwht4096_kernel(const float* __restrict__ in, float* __restrict__ out, int rows_per_cta) {
    __shared__ __align__(16) float s[2 * SROW];

    const int t = threadIdx.x;
    const long row0 = (long)blockIdx.x * rows_per_cta;

    uint32_t sbase;
    asm("{ .reg .u64 tmp; cvta.to.shared.u64 tmp, %1; cvt.u32.u64 %0, tmp; }"
        : "=r"(sbase) : "l"(s));
    const uint32_t sbuf0 = sbase;
    const uint32_t sbuf1 = sbase + SROW * 4u;

    // Prologue: prefetch row 0 into buffer 0.
    stage_row(sbuf0, reinterpret_cast<const float4*>(in + row0 * ROW), t);

    const int j = t >> 2, r = t & 3;   // round-A ownership

    for (int k = 0; k < rows_per_cta; k++) {
        const int cur = k & 1;
        // Prefetch next row into the other buffer (previous iteration's trailing
        // barrier guarantees nobody still reads it).
        if (k + 1 < rows_per_cta) {
            stage_row(cur ? sbuf0 : sbuf1,
                      reinterpret_cast<const float4*>(in + (row0 + k + 1) * ROW), t);
            cp_wait<1>();   // current row's group complete
        } else {
            cp_wait<0>();
        }
        __syncthreads();

        float* sm = s + cur * SROW;

        // ---- Round A: thread (j,r) owns e = j*256 + m*4 + r, m = 0..63.
        // Skewed word = 260*j + 4*m + r; banks (4j+r) mod 32 per phase -> clean.
        {
            float* base = sm + 260 * j + r;
            float2 v[32];
#pragma unroll
            for (int p = 0; p < 32; p++)
                v[p] = make_float2(base[8 * p], base[8 * p + 4]);
            fwht64p(v);   // butterflies bits [7:2]
#pragma unroll
            for (int p = 0; p < 32; p++) {
                base[8 * p]     = v[p].x;
                base[8 * p + 4] = v[p].y;
            }
        }
        __syncthreads();   // round A scatter -> round B gather

        // ---- Round B: thread t owns e = jj*256 + 4*t + rr (LDS.128 gather),
        // butterflies bits {[11:8],[1:0]}, then scaled coalesced STG.128.
        {
            float2 w[32];
#pragma unroll
            for (int jj = 0; jj < 16; jj++) {
                float4 q = *reinterpret_cast<const float4*>(sm + 260 * jj + 4 * t);
                w[2 * jj]     = make_float2(q.x, q.y);
                w[2 * jj + 1] = make_float2(q.z, q.w);
            }
            fwht64p(w);

            const float2 SC = make_float2(1.0f / 64.0f, 1.0f / 64.0f);
            float4* y4 = reinterpret_cast<float4*>(out + (row0 + k) * ROW);
#pragma unroll
            for (int jj = 0; jj < 16; jj++) {
                float2 lo = fmul2(w[2 * jj], SC);
                float2 hi = fmul2(w[2 * jj + 1], SC);
                float4 o;
                o.x = lo.x; o.y = lo.y; o.z = hi.x; o.w = hi.y;
                y4[jj * 64 + t] = o;
            }
        }
        // Trailing barrier: protects buf[cur] before next iteration's prefetch.
        __syncthreads();
    }
}

extern "C" void kernel_launch(void* const* d_in, const int* in_sizes, int n_in,
                              void* d_out, int out_size) {
    const float* x = (const float*)d_in[0];
    float* y = (float*)d_out;
    int total = in_sizes[0];
    int nrows = total / ROW;                      // 8192
    int nctas = nrows / RPC;                      // 4096
    int rpc = RPC;
    if (nrows % RPC != 0) { nctas = nrows; rpc = 1; }
    fwht4096_kernel<<<nctas, TPR>>>(x, y, rpc);
}